// round 16
// baseline (speedup 1.0000x reference)
#include <cuda_runtime.h>
#include <cstdint>
#include <cstddef>

// ---------------------------------------------------------------------------
// MSReversibleRefine: B=4, DIM=64, HP=32, NHEAD=8, WS=16, H=W=128
//   d_in: 0 reused_attn (256,8,256,256) | 1 refined_lms (4,64,128,128)
//         2 hp_in (4,32,128,128) | 3 ra_w1 (8,8,1,3) | 4 ra_w2 (8,8,1,1)
//         5 ra_b2 (8) | 6 dw_w (64,1,3,3) | 7 dw_b (64) | 8 pw_w (64,64,1,1)
//         9 pw_b (64) | 10 fuse_w (64,96,3,3) | 11 fuse_b (64)
//   d_out: attn (134217728 f32) ++ out (4194304 f32)
// ---------------------------------------------------------------------------
#define ATTN_ELEMS 134217728LL
#define FULLM 0xffffffffu

typedef unsigned long long ull;

// f32x2 packed helpers (SASS FFMA2 — only reachable via PTX)
__device__ __forceinline__ ull pk2(float lo, float hi) {
    ull r; asm("mov.b64 %0, {%1, %2};" : "=l"(r) : "f"(lo), "f"(hi)); return r;
}
__device__ __forceinline__ void upk2(float& lo, float& hi, ull v) {
    asm("mov.b64 {%0, %1}, %2;" : "=f"(lo), "=f"(hi) : "l"(v));
}
__device__ __forceinline__ ull fma2(ull a, ull b, ull c) {
    ull d; asm("fma.rn.f32x2 %0, %1, %2, %3;" : "=l"(d) : "l"(a), "l"(b), "l"(c)); return d;
}

// scratch (static device globals: the sanctioned no-alloc workaround)
__device__ __align__(128) float g_refl[4 * 64 * 128 * 128]; // reflashed
__device__ __align__(128) float g_res [4 * 64 * 128 * 128]; // pw + reflashed
__device__ __align__(128) float g_fw  [96 * 9 * 64];        // fuse w: [c][tap][o]
__device__ __align__(128) float g_eff [200];                // [h][24 coeffs + bias]

// ---------------------------------------------------------------------------
// prep: eff[h][ci][dx] = sum_co w2[h,co]*w1[co,ci,dx]; transpose fuse weights
// ---------------------------------------------------------------------------
__global__ void prep_kernel(const float* __restrict__ w1, const float* __restrict__ w2,
                            const float* __restrict__ b2, const float* __restrict__ fw)
{
    int t = blockIdx.x * 256 + threadIdx.x;
    if (t < 200) {
        int h = t / 25, k = t % 25;
        if (k < 24) {
            int ci = k / 3, dx = k % 3;
            float s = 0.f;
            #pragma unroll
            for (int co = 0; co < 8; co++)
                s += w2[h * 8 + co] * w1[(co * 8 + ci) * 3 + dx];
            g_eff[h * 25 + k] = s;
        } else {
            g_eff[h * 25 + 24] = b2[h];
        }
    }
    if (t < 96 * 9 * 64) {
        int o = t & 63;
        int r = t >> 6;
        int tap = r % 9;
        int c = r / 9;
        g_fw[t] = fw[(o * 96 + c) * 9 + tap];
    }
}

// ---------------------------------------------------------------------------
// attn kernel (scalar stencil): one block per window (256 blocks), warp = head.
// eff-conv -> relu -> warp softmax -> STG attn, + fused einsum in registers.
// ---------------------------------------------------------------------------
__global__ __launch_bounds__(256, 2)
void attn_kernel(const float* __restrict__ reused,
                 const float* __restrict__ refined,
                 float* __restrict__ attn_out)
{
    extern __shared__ float sm[];
    float* xw  = sm;                       // 64*256 window pixels [ch][m]
    float* buf = sm + 64 * 256;            // 2 * 8 * 256 row double buffer
    float* eff = sm + 64 * 256 + 2 * 2048; // 200

    const int bw   = blockIdx.x;
    const int tid  = threadIdx.x;
    const int h    = tid >> 5;
    const int lane = tid & 31;

    const int b  = bw >> 6;
    const int g1 = (bw >> 3) & 7;
    const int g2 = bw & 7;

    for (int i = tid; i < 200; i += 256) eff[i] = g_eff[i];

    // load window pixels: xw[ch*256 + m] = refined[b, ch, (m>>4)*8+g1, (m&15)*8+g2]
    {
        const float* rbase = refined + (size_t)b * 64 * 16384;
        for (int i = tid; i < 16384; i += 256) {
            int ch = i >> 8, m = i & 255;
            int y = ((m >> 4) << 3) + g1;
            int x = ((m & 15) << 3) + g2;
            xw[i] = rbase[ch * 16384 + y * 128 + x];
        }
    }

    float acc[8][8];
    #pragma unroll
    for (int d = 0; d < 8; d++)
        #pragma unroll
        for (int i = 0; i < 8; i++) acc[d][i] = 0.f;

    const size_t rowbase = (size_t)(bw * 8 + h) * 65536; // + m*256 per row

    // preload row m=0 (warp h loads channel h)
    {
        const float4* rl = (const float4*)(reused + rowbase);
        float4 la = __ldg(rl + lane);
        float4 lb = __ldg(rl + 32 + lane);
        float4* bp = (float4*)(buf + h * 256);
        int c0 = lane,      s0 = c0 ^ ((c0 >> 3) & 7);
        int c1 = 32 + lane, s1 = c1 ^ ((c1 >> 3) & 7);
        bp[s0] = la;
        bp[s1] = lb;
    }
    __syncthreads();

    const float bias = eff[h * 25 + 24];
    const int cA = 2 * lane;
    const int cB = cA + 1;
    const int sA = cA ^ ((cA >> 3) & 7);
    const int sB = cB ^ ((cB >> 3) & 7);

    #pragma unroll 1
    for (int m = 0; m < 256; m++) {
        const int ph = m & 1;
        const bool pre = (m + 1 < 256);
        float4 la, lb;
        if (pre) {
            const float4* rl = (const float4*)(reused + rowbase + (size_t)(m + 1) * 256);
            la = __ldg(rl + lane);
            lb = __ldg(rl + 32 + lane);
        }

        // effective 8x8x3 stencil
        float a[8];
        #pragma unroll
        for (int i = 0; i < 8; i++) a[i] = bias;

        const float4* rp = (const float4*)(buf + ph * 2048);
        #pragma unroll
        for (int c = 0; c < 8; c++) {
            float4 va = rp[c * 64 + sA];
            float4 vb = rp[c * 64 + sB];
            float v[8] = {va.x, va.y, va.z, va.w, vb.x, vb.y, vb.z, vb.w};
            float lh = __shfl_up_sync(FULLM, v[7], 1);
            float rh = __shfl_down_sync(FULLM, v[0], 1);
            if (lane == 0)  lh = 0.f;
            if (lane == 31) rh = 0.f;
            float e0 = eff[h * 25 + c * 3 + 0];
            float e1 = eff[h * 25 + c * 3 + 1];
            float e2 = eff[h * 25 + c * 3 + 2];
            #pragma unroll
            for (int i = 0; i < 8; i++) {
                float L = (i == 0) ? lh : v[i - 1];
                float R = (i == 7) ? rh : v[i + 1];
                a[i] = fmaf(e0, L, a[i]);
                a[i] = fmaf(e1, v[i], a[i]);
                a[i] = fmaf(e2, R, a[i]);
            }
        }

        // relu + warp softmax over 256 (8 per lane)
        float mx = 0.f;
        #pragma unroll
        for (int i = 0; i < 8; i++) { a[i] = fmaxf(a[i], 0.f); mx = fmaxf(mx, a[i]); }
        #pragma unroll
        for (int o = 16; o; o >>= 1) mx = fmaxf(mx, __shfl_xor_sync(FULLM, mx, o));
        float sum = 0.f;
        #pragma unroll
        for (int i = 0; i < 8; i++) { a[i] = __expf(a[i] - mx); sum += a[i]; }
        #pragma unroll
        for (int o = 16; o; o >>= 1) sum += __shfl_xor_sync(FULLM, sum, o);
        float inv = __fdividef(1.f, sum);
        #pragma unroll
        for (int i = 0; i < 8; i++) a[i] *= inv;

        // store attn row (two STG.128 per lane, warp-coalesced)
        {
            float4* op = (float4*)(attn_out + rowbase + (size_t)m * 256);
            op[2 * lane]     = make_float4(a[0], a[1], a[2], a[3]);
            op[2 * lane + 1] = make_float4(a[4], a[5], a[6], a[7]);
        }

        // fused einsum accumulate: acc[d][i] += a[i] * x[h,d,m]
        {
            const float* xcol = xw + (h * 8) * 256 + m;
            #pragma unroll
            for (int d = 0; d < 8; d++) {
                float xv = xcol[d * 256]; // broadcast LDS
                #pragma unroll
                for (int i = 0; i < 8; i++) acc[d][i] = fmaf(a[i], xv, acc[d][i]);
            }
        }

        // stage prefetched row
        if (pre) {
            float4* bp = (float4*)(buf + (ph ^ 1) * 2048 + h * 256);
            int c0 = lane,      s0 = c0 ^ ((c0 >> 3) & 7);
            int c1 = 32 + lane, s1 = c1 ^ ((c1 >> 3) & 7);
            bp[s0] = la;
            bp[s1] = lb;
        }
        __syncthreads();
    }

    // scatter reflashed: g_refl[b, h*8+d, (n>>4)*8+g1, (n&15)*8+g2]
    {
        float* gout = g_refl + ((size_t)b * 64 + h * 8) * 16384;
        #pragma unroll
        for (int d = 0; d < 8; d++) {
            #pragma unroll
            for (int i = 0; i < 8; i++) {
                int n = lane * 8 + i;
                int y = ((n >> 4) << 3) + g1;
                int x = ((n & 15) << 3) + g2;
                gout[d * 16384 + y * 128 + x] = acc[d][i];
            }
        }
    }
}

// ---------------------------------------------------------------------------
// merged depthwise 3x3 + relu + pointwise 64->64 + residual : g_refl -> g_res
// ---------------------------------------------------------------------------
__global__ __launch_bounds__(256, 2)
void dwpw_kernel(const float* __restrict__ dww, const float* __restrict__ dwb,
                 const float* __restrict__ pww, const float* __restrict__ pwb)
{
    __shared__ float tile[8 * 324];   // 8 ch x 18x18
    __shared__ float pwsh[4096];
    __shared__ float pwbsh[64];
    __shared__ float dwsh[576];
    __shared__ float dwbsh[64];

    int b   = blockIdx.z;
    int tyb = blockIdx.y * 16;
    int txb = blockIdx.x * 16;
    int tid = threadIdx.x;
    int tx  = tid & 15, ty = tid >> 4;

    for (int i = tid; i < 4096; i += 256) pwsh[i] = pww[i];
    for (int i = tid; i < 576;  i += 256) dwsh[i] = dww[i];
    if (tid < 64) { pwbsh[tid] = pwb[tid]; dwbsh[tid] = dwb[tid]; }

    ull dwp[32];

    for (int cc = 0; cc < 64; cc += 8) {
        __syncthreads();
        for (int i = tid; i < 8 * 324; i += 256) {
            int c = i / 324, r = i % 324;
            int iy = r / 18, ix = r % 18;
            int y = tyb + iy - 1, x = txb + ix - 1;
            float v = 0.f;
            if ((unsigned)y < 128u && (unsigned)x < 128u)
                v = g_refl[((size_t)b * 64 + cc + c) * 16384 + y * 128 + x];
            tile[i] = v;
        }
        __syncthreads();

        float sv[8];
        #pragma unroll
        for (int c = 0; c < 8; c++) {
            const float* w = dwsh + (cc + c) * 9;
            float s = dwbsh[cc + c];
            #pragma unroll
            for (int tap = 0; tap < 9; tap++) {
                int dy = tap / 3, dx = tap % 3;
                s = fmaf(w[tap], tile[c * 324 + (ty + dy) * 18 + (tx + dx)], s);
            }
            sv[c] = fmaxf(s, 0.f);
        }
        #pragma unroll
        for (int j = 0; j < 4; j++)
            dwp[(cc >> 1) + j] = pk2(sv[2 * j], sv[2 * j + 1]);
    }

    int y = tyb + ty, x = txb + tx;
    size_t pix = (size_t)y * 128 + x;
    const float* rin = g_refl + (size_t)b * 64 * 16384 + pix;
    float*       ro  = g_res  + (size_t)b * 64 * 16384 + pix;

    #pragma unroll 4
    for (int o = 0; o < 64; o++) {
        ull acc2 = 0ull;
        const ulonglong2* wr = (const ulonglong2*)(pwsh + o * 64);
        #pragma unroll
        for (int c4 = 0; c4 < 16; c4++) {
            ulonglong2 uw = wr[c4];
            acc2 = fma2(uw.x, dwp[2 * c4],     acc2);
            acc2 = fma2(uw.y, dwp[2 * c4 + 1], acc2);
        }
        float lo, hi;
        upk2(lo, hi, acc2);
        ro[o * 16384] = lo + hi + pwbsh[o] + rin[o * 16384];
    }
}

// ---------------------------------------------------------------------------
// fuse conv 3x3 (96 -> 64) + bias, then out = g_refl * conv.
// lane <-> o-pair, weights in registers (coalesced LDG.64), v broadcast
// LDS.64 from duplicated (v,v) tile. smem cut to 28.4KB (2-pass epilogue)
// + launch_bounds(128,4) -> 4 blocks/SM (16 warps) to hide LDS/LDG latency.
// ---------------------------------------------------------------------------
__global__ __launch_bounds__(128, 4)
void fuse_kernel(const float* __restrict__ hp, const float* __restrict__ fb,
                 float* __restrict__ out)
{
    __shared__ ull   tileu[8 * 180];      // 8 ch x 10x18, each elem = (v,v)  11520 B
    __shared__ float sacc[64 * 66];       // half-tile transpose buffer       16896 B

    const int b   = blockIdx.z;
    const int tyb = blockIdx.y * 8;
    const int txb = blockIdx.x * 16;
    const int tid = threadIdx.x;
    const int w   = tid >> 5;             // warp 0..3
    const int lane = tid & 31;

    ull acc[32];
    #pragma unroll
    for (int p = 0; p < 32; p++) acc[p] = 0ull;

    const ull* wbase = (const ull*)g_fw;  // pair index = (c*9+tap)*32 + lane

    #pragma unroll 1
    for (int cc = 0; cc < 96; cc += 8) {
        __syncthreads();
        // stage 8-channel 10x18 duplicated tile with zero-pad halo (no big divs)
        #pragma unroll 1
        for (int c = 0; c < 8; c++) {
            for (int r = tid; r < 180; r += 128) {
                int iy = r / 18, ix = r - iy * 18;
                int y = tyb + iy - 1, x = txb + ix - 1;
                float v = 0.f;
                if ((unsigned)y < 128u && (unsigned)x < 128u) {
                    int ch = cc + c;
                    v = (ch < 64)
                        ? g_res[((size_t)b * 64 + ch) * 16384 + y * 128 + x]
                        : hp  [((size_t)b * 32 + (ch - 64)) * 16384 + y * 128 + x];
                }
                tileu[c * 180 + r] = pk2(v, v);
            }
        }
        __syncthreads();

        #pragma unroll 1
        for (int c = 0; c < 8; c++) {
            // weights for this channel into registers (lane-coalesced LDG.64)
            ull wreg[9];
            const int cg = cc + c;
            #pragma unroll
            for (int tap = 0; tap < 9; tap++)
                wreg[tap] = __ldg(wbase + (cg * 9 + tap) * 32 + lane);

            // warp-uniform base for this channel + warp's row strip
            const ull* tp = tileu + c * 180 + (2 * w) * 18;
            #pragma unroll
            for (int p = 0; p < 32; p++) {
                const ull* pp = tp + (p >> 4) * 18 + (p & 15);
                #pragma unroll
                for (int tap = 0; tap < 9; tap++) {
                    ull v2 = pp[(tap / 3) * 18 + (tap % 3)]; // broadcast LDS.64
                    acc[p] = fma2(wreg[tap], v2, acc[p]);
                }
            }
        }
    }

    // 2-pass transpose epilogue (half = pixel-row parity within warp strip)
    #pragma unroll 1
    for (int half = 0; half < 2; half++) {
        __syncthreads();
        #pragma unroll
        for (int q = 0; q < 16; q++) {
            int p = half * 16 + q;
            float lo, hi;
            upk2(lo, hi, acc[p]);
            ((float2*)sacc)[(w * 16 + q) * 33 + lane] = make_float2(lo, hi);
        }
        __syncthreads();
        for (int i = tid; i < 4096; i += 128) {
            int px = i & 15;
            int o  = (i >> 4) & 63;
            int wq = i >> 10;               // source warp 0..3
            float v = sacc[(wq * 16 + px) * 66 + o] + fb[o];
            size_t idx = ((size_t)b * 64 + o) * 16384 +
                         (size_t)(tyb + 2 * wq + half) * 128 + (txb + px);
            out[idx] = g_refl[idx] * v;
        }
    }
}

// ---------------------------------------------------------------------------
extern "C" void kernel_launch(void* const* d_in, const int* in_sizes, int n_in,
                              void* d_out, int out_size)
{
    const float* reused  = (const float*)d_in[0];
    const float* refined = (const float*)d_in[1];
    const float* hp      = (const float*)d_in[2];
    const float* ra_w1   = (const float*)d_in[3];
    const float* ra_w2   = (const float*)d_in[4];
    const float* ra_b2   = (const float*)d_in[5];
    const float* dw_w    = (const float*)d_in[6];
    const float* dw_b    = (const float*)d_in[7];
    const float* pw_w    = (const float*)d_in[8];
    const float* pw_b    = (const float*)d_in[9];
    const float* fuse_w  = (const float*)d_in[10];
    const float* fuse_b  = (const float*)d_in[11];

    float* attn_out = (float*)d_out;
    float* out_out  = (float*)d_out + ATTN_ELEMS;

    // 1. weight prep
    prep_kernel<<<216, 256>>>(ra_w1, ra_w2, ra_b2, fuse_w);

    // 2. fused attn-conv + softmax + einsum
    const int smem = (64 * 256 + 2 * 2048 + 200) * (int)sizeof(float); // 82720
    cudaFuncSetAttribute(attn_kernel, cudaFuncAttributeMaxDynamicSharedMemorySize, smem);
    attn_kernel<<<256, 256, smem>>>(reused, refined, attn_out);

    // 3. depthwise + relu + pointwise + residual (merged)
    dwpw_kernel<<<dim3(8, 8, 4), 256>>>(dw_w, dw_b, pw_w, pw_b);

    // 4. fuse conv + gate (register-weight layout, 4 blocks/SM)
    fuse_kernel<<<dim3(8, 16, 4), 128>>>(hp, fuse_b, out_out);
}

// round 17
// speedup vs baseline: 1.0715x; 1.0715x over previous
#include <cuda_runtime.h>
#include <cstdint>
#include <cstddef>

// ---------------------------------------------------------------------------
// MSReversibleRefine: B=4, DIM=64, HP=32, NHEAD=8, WS=16, H=W=128
//   d_in: 0 reused_attn (256,8,256,256) | 1 refined_lms (4,64,128,128)
//         2 hp_in (4,32,128,128) | 3 ra_w1 (8,8,1,3) | 4 ra_w2 (8,8,1,1)
//         5 ra_b2 (8) | 6 dw_w (64,1,3,3) | 7 dw_b (64) | 8 pw_w (64,64,1,1)
//         9 pw_b (64) | 10 fuse_w (64,96,3,3) | 11 fuse_b (64)
//   d_out: attn (134217728 f32) ++ out (4194304 f32)
// ---------------------------------------------------------------------------
#define ATTN_ELEMS 134217728LL
#define FULLM 0xffffffffu

typedef unsigned long long ull;

// f32x2 packed helpers (SASS FFMA2 — only reachable via PTX)
__device__ __forceinline__ ull pk2(float lo, float hi) {
    ull r; asm("mov.b64 %0, {%1, %2};" : "=l"(r) : "f"(lo), "f"(hi)); return r;
}
__device__ __forceinline__ void upk2(float& lo, float& hi, ull v) {
    asm("mov.b64 {%0, %1}, %2;" : "=f"(lo), "=f"(hi) : "l"(v));
}
__device__ __forceinline__ ull fma2(ull a, ull b, ull c) {
    ull d; asm("fma.rn.f32x2 %0, %1, %2, %3;" : "=l"(d) : "l"(a), "l"(b), "l"(c)); return d;
}

// scratch (static device globals: the sanctioned no-alloc workaround)
__device__ __align__(128) float g_refl[4 * 64 * 128 * 128]; // reflashed
__device__ __align__(128) float g_res [4 * 64 * 128 * 128]; // pw + reflashed
__device__ __align__(128) float g_fw  [96 * 9 * 64];        // fuse w: [c][tap][o]
__device__ __align__(128) float g_eff [200];                // [h][24 coeffs + bias]

// ---------------------------------------------------------------------------
// prep: eff[h][ci][dx] = sum_co w2[h,co]*w1[co,ci,dx]; transpose fuse weights
// ---------------------------------------------------------------------------
__global__ void prep_kernel(const float* __restrict__ w1, const float* __restrict__ w2,
                            const float* __restrict__ b2, const float* __restrict__ fw)
{
    int t = blockIdx.x * 256 + threadIdx.x;
    if (t < 200) {
        int h = t / 25, k = t % 25;
        if (k < 24) {
            int ci = k / 3, dx = k % 3;
            float s = 0.f;
            #pragma unroll
            for (int co = 0; co < 8; co++)
                s += w2[h * 8 + co] * w1[(co * 8 + ci) * 3 + dx];
            g_eff[h * 25 + k] = s;
        } else {
            g_eff[h * 25 + 24] = b2[h];
        }
    }
    if (t < 96 * 9 * 64) {
        int o = t & 63;
        int r = t >> 6;
        int tap = r % 9;
        int c = r / 9;
        g_fw[t] = fw[(o * 96 + c) * 9 + tap];
    }
}

// ---------------------------------------------------------------------------
// attn kernel (scalar stencil): one block per window (256 blocks), warp = head.
// eff-conv -> relu -> warp softmax -> STG attn, + fused einsum in registers.
// ---------------------------------------------------------------------------
__global__ __launch_bounds__(256, 2)
void attn_kernel(const float* __restrict__ reused,
                 const float* __restrict__ refined,
                 float* __restrict__ attn_out)
{
    extern __shared__ float sm[];
    float* xw  = sm;                       // 64*256 window pixels [ch][m]
    float* buf = sm + 64 * 256;            // 2 * 8 * 256 row double buffer
    float* eff = sm + 64 * 256 + 2 * 2048; // 200

    const int bw   = blockIdx.x;
    const int tid  = threadIdx.x;
    const int h    = tid >> 5;
    const int lane = tid & 31;

    const int b  = bw >> 6;
    const int g1 = (bw >> 3) & 7;
    const int g2 = bw & 7;

    for (int i = tid; i < 200; i += 256) eff[i] = g_eff[i];

    // load window pixels: xw[ch*256 + m] = refined[b, ch, (m>>4)*8+g1, (m&15)*8+g2]
    {
        const float* rbase = refined + (size_t)b * 64 * 16384;
        for (int i = tid; i < 16384; i += 256) {
            int ch = i >> 8, m = i & 255;
            int y = ((m >> 4) << 3) + g1;
            int x = ((m & 15) << 3) + g2;
            xw[i] = rbase[ch * 16384 + y * 128 + x];
        }
    }

    float acc[8][8];
    #pragma unroll
    for (int d = 0; d < 8; d++)
        #pragma unroll
        for (int i = 0; i < 8; i++) acc[d][i] = 0.f;

    const size_t rowbase = (size_t)(bw * 8 + h) * 65536; // + m*256 per row

    // preload row m=0 (warp h loads channel h)
    {
        const float4* rl = (const float4*)(reused + rowbase);
        float4 la = __ldg(rl + lane);
        float4 lb = __ldg(rl + 32 + lane);
        float4* bp = (float4*)(buf + h * 256);
        int c0 = lane,      s0 = c0 ^ ((c0 >> 3) & 7);
        int c1 = 32 + lane, s1 = c1 ^ ((c1 >> 3) & 7);
        bp[s0] = la;
        bp[s1] = lb;
    }
    __syncthreads();

    const float bias = eff[h * 25 + 24];
    const int cA = 2 * lane;
    const int cB = cA + 1;
    const int sA = cA ^ ((cA >> 3) & 7);
    const int sB = cB ^ ((cB >> 3) & 7);

    #pragma unroll 1
    for (int m = 0; m < 256; m++) {
        const int ph = m & 1;
        const bool pre = (m + 1 < 256);
        float4 la, lb;
        if (pre) {
            const float4* rl = (const float4*)(reused + rowbase + (size_t)(m + 1) * 256);
            la = __ldg(rl + lane);
            lb = __ldg(rl + 32 + lane);
        }

        // effective 8x8x3 stencil
        float a[8];
        #pragma unroll
        for (int i = 0; i < 8; i++) a[i] = bias;

        const float4* rp = (const float4*)(buf + ph * 2048);
        #pragma unroll
        for (int c = 0; c < 8; c++) {
            float4 va = rp[c * 64 + sA];
            float4 vb = rp[c * 64 + sB];
            float v[8] = {va.x, va.y, va.z, va.w, vb.x, vb.y, vb.z, vb.w};
            float lh = __shfl_up_sync(FULLM, v[7], 1);
            float rh = __shfl_down_sync(FULLM, v[0], 1);
            if (lane == 0)  lh = 0.f;
            if (lane == 31) rh = 0.f;
            float e0 = eff[h * 25 + c * 3 + 0];
            float e1 = eff[h * 25 + c * 3 + 1];
            float e2 = eff[h * 25 + c * 3 + 2];
            #pragma unroll
            for (int i = 0; i < 8; i++) {
                float L = (i == 0) ? lh : v[i - 1];
                float R = (i == 7) ? rh : v[i + 1];
                a[i] = fmaf(e0, L, a[i]);
                a[i] = fmaf(e1, v[i], a[i]);
                a[i] = fmaf(e2, R, a[i]);
            }
        }

        // relu + warp softmax over 256 (8 per lane)
        float mx = 0.f;
        #pragma unroll
        for (int i = 0; i < 8; i++) { a[i] = fmaxf(a[i], 0.f); mx = fmaxf(mx, a[i]); }
        #pragma unroll
        for (int o = 16; o; o >>= 1) mx = fmaxf(mx, __shfl_xor_sync(FULLM, mx, o));
        float sum = 0.f;
        #pragma unroll
        for (int i = 0; i < 8; i++) { a[i] = __expf(a[i] - mx); sum += a[i]; }
        #pragma unroll
        for (int o = 16; o; o >>= 1) sum += __shfl_xor_sync(FULLM, sum, o);
        float inv = __fdividef(1.f, sum);
        #pragma unroll
        for (int i = 0; i < 8; i++) a[i] *= inv;

        // store attn row (two STG.128 per lane, warp-coalesced)
        {
            float4* op = (float4*)(attn_out + rowbase + (size_t)m * 256);
            op[2 * lane]     = make_float4(a[0], a[1], a[2], a[3]);
            op[2 * lane + 1] = make_float4(a[4], a[5], a[6], a[7]);
        }

        // fused einsum accumulate: acc[d][i] += a[i] * x[h,d,m]
        {
            const float* xcol = xw + (h * 8) * 256 + m;
            #pragma unroll
            for (int d = 0; d < 8; d++) {
                float xv = xcol[d * 256]; // broadcast LDS
                #pragma unroll
                for (int i = 0; i < 8; i++) acc[d][i] = fmaf(a[i], xv, acc[d][i]);
            }
        }

        // stage prefetched row
        if (pre) {
            float4* bp = (float4*)(buf + (ph ^ 1) * 2048 + h * 256);
            int c0 = lane,      s0 = c0 ^ ((c0 >> 3) & 7);
            int c1 = 32 + lane, s1 = c1 ^ ((c1 >> 3) & 7);
            bp[s0] = la;
            bp[s1] = lb;
        }
        __syncthreads();
    }

    // scatter reflashed: g_refl[b, h*8+d, (n>>4)*8+g1, (n&15)*8+g2]
    {
        float* gout = g_refl + ((size_t)b * 64 + h * 8) * 16384;
        #pragma unroll
        for (int d = 0; d < 8; d++) {
            #pragma unroll
            for (int i = 0; i < 8; i++) {
                int n = lane * 8 + i;
                int y = ((n >> 4) << 3) + g1;
                int x = ((n & 15) << 3) + g2;
                gout[d * 16384 + y * 128 + x] = acc[d][i];
            }
        }
    }
}

// ---------------------------------------------------------------------------
// merged depthwise 3x3 + relu + pointwise 64->64 + residual : g_refl -> g_res
// ---------------------------------------------------------------------------
__global__ __launch_bounds__(256, 2)
void dwpw_kernel(const float* __restrict__ dww, const float* __restrict__ dwb,
                 const float* __restrict__ pww, const float* __restrict__ pwb)
{
    __shared__ float tile[8 * 324];   // 8 ch x 18x18
    __shared__ float pwsh[4096];
    __shared__ float pwbsh[64];
    __shared__ float dwsh[576];
    __shared__ float dwbsh[64];

    int b   = blockIdx.z;
    int tyb = blockIdx.y * 16;
    int txb = blockIdx.x * 16;
    int tid = threadIdx.x;
    int tx  = tid & 15, ty = tid >> 4;

    for (int i = tid; i < 4096; i += 256) pwsh[i] = pww[i];
    for (int i = tid; i < 576;  i += 256) dwsh[i] = dww[i];
    if (tid < 64) { pwbsh[tid] = pwb[tid]; dwbsh[tid] = dwb[tid]; }

    ull dwp[32];

    for (int cc = 0; cc < 64; cc += 8) {
        __syncthreads();
        for (int i = tid; i < 8 * 324; i += 256) {
            int c = i / 324, r = i % 324;
            int iy = r / 18, ix = r % 18;
            int y = tyb + iy - 1, x = txb + ix - 1;
            float v = 0.f;
            if ((unsigned)y < 128u && (unsigned)x < 128u)
                v = g_refl[((size_t)b * 64 + cc + c) * 16384 + y * 128 + x];
            tile[i] = v;
        }
        __syncthreads();

        float sv[8];
        #pragma unroll
        for (int c = 0; c < 8; c++) {
            const float* w = dwsh + (cc + c) * 9;
            float s = dwbsh[cc + c];
            #pragma unroll
            for (int tap = 0; tap < 9; tap++) {
                int dy = tap / 3, dx = tap % 3;
                s = fmaf(w[tap], tile[c * 324 + (ty + dy) * 18 + (tx + dx)], s);
            }
            sv[c] = fmaxf(s, 0.f);
        }
        #pragma unroll
        for (int j = 0; j < 4; j++)
            dwp[(cc >> 1) + j] = pk2(sv[2 * j], sv[2 * j + 1]);
    }

    int y = tyb + ty, x = txb + tx;
    size_t pix = (size_t)y * 128 + x;
    const float* rin = g_refl + (size_t)b * 64 * 16384 + pix;
    float*       ro  = g_res  + (size_t)b * 64 * 16384 + pix;

    #pragma unroll 4
    for (int o = 0; o < 64; o++) {
        ull acc2 = 0ull;
        const ulonglong2* wr = (const ulonglong2*)(pwsh + o * 64);
        #pragma unroll
        for (int c4 = 0; c4 < 16; c4++) {
            ulonglong2 uw = wr[c4];
            acc2 = fma2(uw.x, dwp[2 * c4],     acc2);
            acc2 = fma2(uw.y, dwp[2 * c4 + 1], acc2);
        }
        float lo, hi;
        upk2(lo, hi, acc2);
        ro[o * 16384] = lo + hi + pwbsh[o] + rin[o * 16384];
    }
}

// ---------------------------------------------------------------------------
// fuse conv 3x3 (96 -> 64) + bias, then out = g_refl * conv.
// lane <-> o-pair (weights in regs), warp <-> one output row of 16 pixels.
// Row-register reuse: per (channel,dy) load the 18-value input row ONCE
// (18 independent broadcast LDS.64), then 48 register-only FFMA2.
// LDS count/channel: 54 (was 288) -> fma-pipe-bound.
// Block = 128 thr = 4 warps = 16x4 tile; grid = 8 x 32 x 4 = 1024 blocks.
// ---------------------------------------------------------------------------
__global__ __launch_bounds__(128)
void fuse_kernel(const float* __restrict__ hp, const float* __restrict__ fb,
                 float* __restrict__ out)
{
    __shared__ ull   tileu[8 * 108];      // 8 ch x 6 rows x 18 (v,v)   6912 B
    __shared__ float sacc[64 * 66];       // 64 px x 64 o (+pad)       16896 B

    const int b   = blockIdx.z;
    const int tyb = blockIdx.y * 4;
    const int txb = blockIdx.x * 16;
    const int tid = threadIdx.x;
    const int w   = tid >> 5;             // warp = output row in tile
    const int lane = tid & 31;

    ull acc[16];
    #pragma unroll
    for (int p = 0; p < 16; p++) acc[p] = 0ull;

    const ull* wbase = (const ull*)g_fw;  // pair index = (c*9+tap)*32 + lane

    #pragma unroll 1
    for (int cc = 0; cc < 96; cc += 8) {
        __syncthreads();
        // stage 8-channel 6x18 duplicated tile with zero-pad halo
        #pragma unroll 1
        for (int c = 0; c < 8; c++) {
            if (tid < 108) {
                int iy = tid / 18, ix = tid - iy * 18;
                int y = tyb + iy - 1, x = txb + ix - 1;
                float v = 0.f;
                if ((unsigned)y < 128u && (unsigned)x < 128u) {
                    int ch = cc + c;
                    v = (ch < 64)
                        ? g_res[((size_t)b * 64 + ch) * 16384 + y * 128 + x]
                        : hp  [((size_t)b * 32 + (ch - 64)) * 16384 + y * 128 + x];
                }
                tileu[c * 108 + tid] = pk2(v, v);
            }
        }
        __syncthreads();

        #pragma unroll 1
        for (int c = 0; c < 8; c++) {
            // weights for this channel into registers (lane-coalesced LDG.64)
            ull wreg[9];
            const int cg = cc + c;
            #pragma unroll
            for (int tap = 0; tap < 9; tap++)
                wreg[tap] = __ldg(wbase + (cg * 9 + tap) * 32 + lane);

            const ull* tp = tileu + c * 108 + w * 18; // input rows w..w+2
            #pragma unroll
            for (int dy = 0; dy < 3; dy++) {
                // row of 18 values once into registers (broadcast LDS.64 x18)
                ull vrow[18];
                #pragma unroll
                for (int q = 0; q < 18; q++) vrow[q] = tp[dy * 18 + q];
                #pragma unroll
                for (int dx = 0; dx < 3; dx++) {
                    ull wv = wreg[dy * 3 + dx];
                    #pragma unroll
                    for (int p = 0; p < 16; p++)
                        acc[p] = fma2(wv, vrow[p + dx], acc[p]); // reg-only FFMA2
                }
            }
        }
    }

    // transpose epilogue: warp w owns tile row w (16 px)
    __syncthreads();
    #pragma unroll
    for (int q = 0; q < 16; q++) {
        float lo, hi;
        upk2(lo, hi, acc[q]);
        ((float2*)sacc)[(w * 16 + q) * 33 + lane] = make_float2(lo, hi);
    }
    __syncthreads();
    for (int i = tid; i < 4096; i += 128) {
        int px = i & 15;
        int o  = (i >> 4) & 63;
        int wr = i >> 10;                 // tile row
        float v = sacc[(wr * 16 + px) * 66 + o] + fb[o];
        size_t idx = ((size_t)b * 64 + o) * 16384 +
                     (size_t)(tyb + wr) * 128 + (txb + px);
        out[idx] = g_refl[idx] * v;
    }
}

// ---------------------------------------------------------------------------
extern "C" void kernel_launch(void* const* d_in, const int* in_sizes, int n_in,
                              void* d_out, int out_size)
{
    const float* reused  = (const float*)d_in[0];
    const float* refined = (const float*)d_in[1];
    const float* hp      = (const float*)d_in[2];
    const float* ra_w1   = (const float*)d_in[3];
    const float* ra_w2   = (const float*)d_in[4];
    const float* ra_b2   = (const float*)d_in[5];
    const float* dw_w    = (const float*)d_in[6];
    const float* dw_b    = (const float*)d_in[7];
    const float* pw_w    = (const float*)d_in[8];
    const float* pw_b    = (const float*)d_in[9];
    const float* fuse_w  = (const float*)d_in[10];
    const float* fuse_b  = (const float*)d_in[11];

    float* attn_out = (float*)d_out;
    float* out_out  = (float*)d_out + ATTN_ELEMS;

    // 1. weight prep
    prep_kernel<<<216, 256>>>(ra_w1, ra_w2, ra_b2, fuse_w);

    // 2. fused attn-conv + softmax + einsum
    const int smem = (64 * 256 + 2 * 2048 + 200) * (int)sizeof(float); // 82720
    cudaFuncSetAttribute(attn_kernel, cudaFuncAttributeMaxDynamicSharedMemorySize, smem);
    attn_kernel<<<256, 256, smem>>>(reused, refined, attn_out);

    // 3. depthwise + relu + pointwise + residual (merged)
    dwpw_kernel<<<dim3(8, 8, 4), 256>>>(dw_w, dw_b, pw_w, pw_b);

    // 4. fuse conv + gate (row-register layout, 1024 blocks)
    fuse_kernel<<<dim3(8, 32, 4), 128>>>(hp, fuse_b, out_out);
}